// round 12
// baseline (speedup 1.0000x reference)
#include <cuda_runtime.h>
#include <cuda_fp16.h>
#include <math.h>
#include <stdint.h>

#define B_ROWS 4096
#define D_H    1024
#define K_DIM  2048
#define N_DIM  4096

// ---------------- static device scratch ----------------
__device__ __align__(128) __half g_Ah[(size_t)B_ROWS * K_DIM];
__device__ __align__(128) __half g_Bh[(size_t)N_DIM * K_DIM];   // interleaved rows n' = 4j+g
__device__ __align__(128) float  g_bias[N_DIM];                 // interleaved

// ---------------- helpers ----------------
__device__ __forceinline__ uint32_t smem_u32(const void* p) {
    uint32_t a;
    asm("{ .reg .u64 t; cvta.to.shared.u64 t, %1; cvt.u32.u64 %0, t; }" : "=r"(a) : "l"(p));
    return a;
}
__device__ __forceinline__ void cp_async16(uint32_t dst, const void* src) {
    asm volatile("cp.async.cg.shared.global [%0], [%1], 16;" :: "r"(dst), "l"(src) : "memory");
}
__device__ __forceinline__ void cp_commit() {
    asm volatile("cp.async.commit_group;" ::: "memory");
}
template <int N>
__device__ __forceinline__ void cp_wait() {
    asm volatile("cp.async.wait_group %0;" :: "n"(N) : "memory");
}
__device__ __forceinline__ void ldsm4(uint32_t& r0, uint32_t& r1, uint32_t& r2, uint32_t& r3,
                                      uint32_t addr) {
    asm volatile("ldmatrix.sync.aligned.m8n8.x4.shared.b16 {%0,%1,%2,%3}, [%4];"
                 : "=r"(r0), "=r"(r1), "=r"(r2), "=r"(r3) : "r"(addr));
}
__device__ __forceinline__ void mma16816(float& d0, float& d1, float& d2, float& d3,
                                         uint32_t a0, uint32_t a1, uint32_t a2, uint32_t a3,
                                         uint32_t b0, uint32_t b1) {
    asm volatile(
        "mma.sync.aligned.m16n8k16.row.col.f32.f16.f16.f32 "
        "{%0,%1,%2,%3}, {%4,%5,%6,%7}, {%8,%9}, {%0,%1,%2,%3};"
        : "+f"(d0), "+f"(d1), "+f"(d2), "+f"(d3)
        : "r"(a0), "r"(a1), "r"(a2), "r"(a3), "r"(b0), "r"(b1));
}

// ---------------- merged conversion kernel (one launch) ----------------
__global__ __launch_bounds__(256) void conv_all(
    const float* __restrict__ x, const float* __restrict__ h,
    const float* __restrict__ Wi, const float* __restrict__ Wf,
    const float* __restrict__ Wc, const float* __restrict__ Wo,
    const float* __restrict__ bi, const float* __restrict__ bf_,
    const float* __restrict__ bc, const float* __restrict__ bo)
{
    const int b = blockIdx.x;
    if (b < 8192) {
        size_t e = ((size_t)b * 256 + threadIdx.x) * 4;
        int m = (int)(e >> 11);
        int k = (int)(e & 2047);
        const float* src = (k < 1024) ? &x[(size_t)m * 1024 + k]
                                      : &h[(size_t)m * 1024 + (k - 1024)];
        float4 v = *reinterpret_cast<const float4*>(src);
        *reinterpret_cast<__half2*>(&g_Ah[e]) =
            __halves2half2(__float2half_rn(v.x), __float2half_rn(v.y));
        *reinterpret_cast<__half2*>(&g_Ah[e + 2]) =
            __halves2half2(__float2half_rn(v.z), __float2half_rn(v.w));
    } else if (b < 16384) {
        size_t e = ((size_t)(b - 8192) * 256 + threadIdx.x) * 4;
        int np = (int)(e >> 11);
        int k = (int)(e & 2047);
        int j = np >> 2;
        int g = np & 3;
        const float* W = (g == 0) ? Wi : (g == 1) ? Wf : (g == 2) ? Wc : Wo;
        float4 v = *reinterpret_cast<const float4*>(&W[(size_t)j * K_DIM + k]);
        *reinterpret_cast<__half2*>(&g_Bh[e]) =
            __halves2half2(__float2half_rn(v.x), __float2half_rn(v.y));
        *reinterpret_cast<__half2*>(&g_Bh[e + 2]) =
            __halves2half2(__float2half_rn(v.z), __float2half_rn(v.w));
    } else {
        int idx = (b - 16384) * 256 + threadIdx.x;
        int j = idx >> 2;
        int g = idx & 3;
        g_bias[idx] = (g == 0) ? bi[j] : (g == 1) ? bf_[j] : (g == 2) ? bc[j] : bo[j];
    }
}

// ---------------- persistent fused GEMM + LSTM ----------------
// CTA 128x128, 8 warps (4M x 2N, warp tile 32x64), BK=64, 3-slot ring.
// 304 persistent CTAs (2/SM); continuous K-chunk loop across tiles so the
// pipeline never drains; 2-pass epilogue in the just-freed ring slot.
#define GRIDP 304
#define BK 64
#define OFF_A 0
#define OFF_B 16384
#define STAGE_BYTES 32768
#define NSTAGES 3
#define BIAS_OFF    (NSTAGES * STAGE_BYTES)     // 98304
#define SMEM_TOTAL  (BIAS_OFF + 512)            // 98816
#define NTHREADS 256
#define OUT_C_OFF ((size_t)B_ROWS * D_H)

__global__ __launch_bounds__(NTHREADS, 2) void lstm_fused(const float* __restrict__ cprev,
                                                          float* __restrict__ out) {
    extern __shared__ char smem[];
    const uint32_t sbase = smem_u32(smem);
    const int tid = threadIdx.x;
    const int lane = tid & 31;
    const int wid = tid >> 5;
    const int wm = wid & 3;            // 4 warps along M
    const int wn = wid >> 2;           // 2 warps along N
    const int aw = wm * 32;
    const int bw = wn * 64;

    const int bx = blockIdx.x;
    const int ntiles = (1023 - bx) / GRIDP + 1;   // tiles bx, bx+304, ...
    const int totq = ntiles * 32;                 // global K-chunk counter range

    // load K-chunk q2 (tile q2>>5, k-tile q2&31) into ring slot q2%3
    auto load_stage = [&](int q2) {
        const int t = bx + (q2 >> 5) * GRIDP;
        const int m0L = (t >> 5) << 7;
        const int n0L = (t & 31) << 7;
        const int kt = (q2 & 31) * BK;
        const uint32_t st = sbase + (uint32_t)(q2 % 3) * STAGE_BYTES;
#pragma unroll
        for (int i = 0; i < 4; i++) {
            int id = i * NTHREADS + tid;
            int row = id >> 3, c = id & 7;
            uint32_t so = (uint32_t)(row * 128) + (uint32_t)((c ^ (row & 7)) << 4);
            cp_async16(st + OFF_A + so, g_Ah + (size_t)(m0L + row) * K_DIM + kt + c * 8);
        }
#pragma unroll
        for (int i = 0; i < 4; i++) {
            int id = i * NTHREADS + tid;
            int row = id >> 3, c = id & 7;
            uint32_t so = (uint32_t)(row * 128) + (uint32_t)((c ^ (row & 7)) << 4);
            cp_async16(st + OFF_B + so, g_Bh + (size_t)(n0L + row) * K_DIM + kt + c * 8);
        }
        cp_commit();
    };

    float acc[2][8][4];
#pragma unroll
    for (int i = 0; i < 2; i++)
#pragma unroll
        for (int j = 0; j < 8; j++)
#pragma unroll
            for (int q = 0; q < 4; q++) acc[i][j][q] = 0.0f;

    load_stage(0);
    load_stage(1);

    const int aRow = aw + (lane & 15);
    const int aHi = lane >> 4;
    const int bRow = bw + (lane & 7) + ((lane >> 4) << 3);
    const int bHi = (lane >> 3) & 1;

    for (int q = 0; q < totq; q++) {
        cp_wait<1>();                  // chunk q resident
        __syncthreads();               // all warps finished chunk q-1 (slot being refilled)

        if (q + 2 < totq) load_stage(q + 2);
        else cp_commit();              // keep group accounting uniform

        const uint32_t st = sbase + (uint32_t)(q % 3) * STAGE_BYTES;

#pragma unroll
        for (int ks = 0; ks < BK / 16; ks++) {
            uint32_t aH[2][4], bH[8][2];
#pragma unroll
            for (int mf = 0; mf < 2; mf++) {
                int row = aRow + mf * 16;
                int c = 2 * ks + aHi;
                uint32_t off = row * 128 + ((c ^ (row & 7)) << 4);
                ldsm4(aH[mf][0], aH[mf][1], aH[mf][2], aH[mf][3], st + OFF_A + off);
            }
#pragma unroll
            for (int nf2 = 0; nf2 < 4; nf2++) {
                int row = bRow + nf2 * 16;
                int c = 2 * ks + bHi;
                uint32_t addr = st + OFF_B + row * 128 + ((c ^ (row & 7)) << 4);
                ldsm4(bH[2 * nf2][0], bH[2 * nf2][1], bH[2 * nf2 + 1][0], bH[2 * nf2 + 1][1], addr);
            }
#pragma unroll
            for (int mf = 0; mf < 2; mf++)
#pragma unroll
                for (int nf = 0; nf < 8; nf++)
                    mma16816(acc[mf][nf][0], acc[mf][nf][1], acc[mf][nf][2], acc[mf][nf][3],
                             aH[mf][0], aH[mf][1], aH[mf][2], aH[mf][3], bH[nf][0], bH[nf][1]);
        }

        // ---- end of a tile: fused epilogue in the just-freed ring slot ----
        if ((q & 31) == 31) {
            const int t = bx + (q >> 5) * GRIDP;
            const int m0 = (t >> 5) << 7;
            const int n0 = (t & 31) << 7;

            __syncthreads();           // everyone done reading slot q%3
            float* zs = reinterpret_cast<float*>(smem + (size_t)(q % 3) * STAGE_BYTES); // 64x128 f32
            float* bias_s = reinterpret_cast<float*>(smem + BIAS_OFF);
            if (tid < 128) bias_s[tid] = g_bias[n0 + tid];

#pragma unroll
            for (int hh = 0; hh < 2; hh++) {
                if ((aw >> 6) == hh) {             // warps owning rows [64hh, 64hh+64)
                    const int rl = aw - (hh << 6);
#pragma unroll
                    for (int mf = 0; mf < 2; mf++) {
#pragma unroll
                        for (int nf = 0; nf < 8; nf++) {
                            int r0 = rl + mf * 16 + (lane >> 2);
                            int col = bw + nf * 8 + 2 * (lane & 3);
                            int c0 = col ^ ((r0 & 7) << 3);
                            int c1 = col ^ (((r0 + 8) & 7) << 3);
                            *reinterpret_cast<float2*>(&zs[(size_t)r0 * 128 + c0]) =
                                make_float2(acc[mf][nf][0], acc[mf][nf][1]);
                            *reinterpret_cast<float2*>(&zs[(size_t)(r0 + 8) * 128 + c1]) =
                                make_float2(acc[mf][nf][2], acc[mf][nf][3]);
                        }
                    }
                }
                __syncthreads();
#pragma unroll 2
                for (int r = 0; r < 8; r++) {
                    int idx = r * NTHREADS + tid;  // [0, 2048) quadruples
                    int ml = idx >> 5;
                    int qd = idx & 31;
                    int cc = (4 * qd) ^ ((ml & 7) << 3);
                    float4 z4 = *reinterpret_cast<const float4*>(&zs[(size_t)ml * 128 + cc]);
                    float zi = z4.x + bias_s[4 * qd + 0];
                    float zf = z4.y + bias_s[4 * qd + 1];
                    float zc = z4.z + bias_s[4 * qd + 2];
                    float zo = z4.w + bias_s[4 * qd + 3];
                    int m = m0 + (hh << 6) + ml;
                    int j = (n0 >> 2) + qd;
                    float cp = cprev[(size_t)m * D_H + j];
                    float ig = 1.0f / (1.0f + __expf(-zi));
                    float fg = 1.0f / (1.0f + __expf(-zf));
                    float cg = 2.0f / (1.0f + __expf(-2.0f * zc)) - 1.0f;
                    float og = 1.0f / (1.0f + __expf(-zo));
                    float cn = fg * cp + ig * cg;
                    float hn = og * (2.0f / (1.0f + __expf(-2.0f * cn)) - 1.0f);
                    out[(size_t)m * D_H + j] = hn;
                    out[OUT_C_OFF + (size_t)m * D_H + j] = cn;
                }
                __syncthreads();       // pass data fully consumed before reuse
            }

            // reset accumulators for the next tile
#pragma unroll
            for (int i = 0; i < 2; i++)
#pragma unroll
                for (int j = 0; j < 8; j++)
#pragma unroll
                    for (int p = 0; p < 4; p++) acc[i][j][p] = 0.0f;
        }
    }
}

// ---------------- launch ----------------
extern "C" void kernel_launch(void* const* d_in, const int* in_sizes, int n_in,
                              void* d_out, int out_size)
{
    const float* x  = (const float*)d_in[0];
    const float* h  = (const float*)d_in[1];
    const float* c  = (const float*)d_in[2];
    const float* Wi = (const float*)d_in[3];
    const float* bi = (const float*)d_in[4];
    const float* Wf = (const float*)d_in[5];
    const float* bf = (const float*)d_in[6];
    const float* Wc = (const float*)d_in[7];
    const float* bc = (const float*)d_in[8];
    const float* Wo = (const float*)d_in[9];
    const float* bo = (const float*)d_in[10];
    float* out = (float*)d_out;

    static bool attr_set = false;
    if (!attr_set) {
        cudaFuncSetAttribute(lstm_fused, cudaFuncAttributeMaxDynamicSharedMemorySize, SMEM_TOTAL);
        attr_set = true;
    }

    conv_all<<<16400, 256>>>(x, h, Wi, Wf, Wc, Wo, bi, bf, bc, bo);

    lstm_fused<<<GRIDP, NTHREADS, SMEM_TOTAL>>>(c, out);
}

// round 14
// speedup vs baseline: 1.0441x; 1.0441x over previous
#include <cuda_runtime.h>
#include <cuda_fp16.h>
#include <math.h>
#include <stdint.h>

#define B_ROWS 4096
#define D_H    1024
#define K_DIM  2048
#define N_DIM  4096

// ---------------- static device scratch ----------------
__device__ __align__(128) __half g_Ah[(size_t)B_ROWS * K_DIM];
__device__ __align__(128) __half g_Bh[(size_t)N_DIM * K_DIM];   // interleaved rows n' = 4j+g
__device__ __align__(128) float  g_bias[N_DIM];                 // interleaved

// ---------------- helpers ----------------
__device__ __forceinline__ uint32_t smem_u32(const void* p) {
    uint32_t a;
    asm("{ .reg .u64 t; cvta.to.shared.u64 t, %1; cvt.u32.u64 %0, t; }" : "=r"(a) : "l"(p));
    return a;
}
__device__ __forceinline__ void cp_async16(uint32_t dst, const void* src) {
    asm volatile("cp.async.cg.shared.global [%0], [%1], 16;" :: "r"(dst), "l"(src) : "memory");
}
__device__ __forceinline__ void cp_commit() {
    asm volatile("cp.async.commit_group;" ::: "memory");
}
template <int N>
__device__ __forceinline__ void cp_wait() {
    asm volatile("cp.async.wait_group %0;" :: "n"(N) : "memory");
}
__device__ __forceinline__ void ldsm4(uint32_t& r0, uint32_t& r1, uint32_t& r2, uint32_t& r3,
                                      uint32_t addr) {
    asm volatile("ldmatrix.sync.aligned.m8n8.x4.shared.b16 {%0,%1,%2,%3}, [%4];"
                 : "=r"(r0), "=r"(r1), "=r"(r2), "=r"(r3) : "r"(addr));
}
__device__ __forceinline__ void mma16816(float& d0, float& d1, float& d2, float& d3,
                                         uint32_t a0, uint32_t a1, uint32_t a2, uint32_t a3,
                                         uint32_t b0, uint32_t b1) {
    asm volatile(
        "mma.sync.aligned.m16n8k16.row.col.f32.f16.f16.f32 "
        "{%0,%1,%2,%3}, {%4,%5,%6,%7}, {%8,%9}, {%0,%1,%2,%3};"
        : "+f"(d0), "+f"(d1), "+f"(d2), "+f"(d3)
        : "r"(a0), "r"(a1), "r"(a2), "r"(a3), "r"(b0), "r"(b1));
}

__device__ __forceinline__ float sigm(float z) { return 1.0f / (1.0f + __expf(-z)); }
__device__ __forceinline__ float tanh_fast(float z) {
    return 2.0f / (1.0f + __expf(-2.0f * z)) - 1.0f;
}

// ---------------- merged conversion kernel (one launch, 8 floats/thread) ----
// blocks [0, 4096): A convert; [4096, 8192): B convert; [8192, 8208): bias
__global__ __launch_bounds__(256) void conv_all(
    const float* __restrict__ x, const float* __restrict__ h,
    const float* __restrict__ Wi, const float* __restrict__ Wf,
    const float* __restrict__ Wc, const float* __restrict__ Wo,
    const float* __restrict__ bi, const float* __restrict__ bf_,
    const float* __restrict__ bc, const float* __restrict__ bo)
{
    const int b = blockIdx.x;
    if (b < 8192) {
        const bool isA = (b < 4096);
        size_t e = ((size_t)(isA ? b : b - 4096) * 256 + threadIdx.x) * 8;
        int r = (int)(e >> 11);          // row (m for A, n' for B)
        int k = (int)(e & 2047);         // 8-aligned; never straddles 1024
        const float* src;
        if (isA) {
            src = (k < 1024) ? &x[(size_t)r * 1024 + k]
                             : &h[(size_t)r * 1024 + (k - 1024)];
        } else {
            int j = r >> 2;
            int g = r & 3;
            const float* W = (g == 0) ? Wi : (g == 1) ? Wf : (g == 2) ? Wc : Wo;
            src = &W[(size_t)j * K_DIM + k];
        }
        float4 v0 = *reinterpret_cast<const float4*>(src);
        float4 v1 = *reinterpret_cast<const float4*>(src + 4);
        __half2 o[4];
        o[0] = __halves2half2(__float2half_rn(v0.x), __float2half_rn(v0.y));
        o[1] = __halves2half2(__float2half_rn(v0.z), __float2half_rn(v0.w));
        o[2] = __halves2half2(__float2half_rn(v1.x), __float2half_rn(v1.y));
        o[3] = __halves2half2(__float2half_rn(v1.z), __float2half_rn(v1.w));
        __half* dst = isA ? g_Ah : g_Bh;
        *reinterpret_cast<uint4*>(&dst[e]) = *reinterpret_cast<const uint4*>(o);
    } else {
        int idx = (b - 8192) * 256 + threadIdx.x;
        int j = idx >> 2;
        int g = idx & 3;
        g_bias[idx] = (g == 0) ? bi[j] : (g == 1) ? bf_[j] : (g == 2) ? bc[j] : bo[j];
    }
}

// ---------------- fused GEMM + LSTM (R8 configuration) ----------------
// CTA 128(M) x 128(N'), 8 warps (4M x 2N), warp tile 32x64, BK=64, 3-stage.
// TWO CTAs per SM (launch_bounds(256,2)) for barrier-independent overlap.
#define BK 64
#define OFF_A 0
#define OFF_B 16384
#define STAGE_BYTES 32768
#define NSTAGES 3
#define BIAS_OFF    (NSTAGES * STAGE_BYTES)     // 98304
#define SMEM_TOTAL  (BIAS_OFF + 512)            // 98816
#define NKT (K_DIM / BK)           // 32
#define NTHREADS 256
#define OUT_C_OFF ((size_t)B_ROWS * D_H)

__global__ __launch_bounds__(NTHREADS, 2) void lstm_fused(const float* __restrict__ cprev,
                                                          float* __restrict__ out) {
    extern __shared__ char smem[];
    const uint32_t sbase = smem_u32(smem);
    const int tid = threadIdx.x;
    const int lane = tid & 31;
    const int wid = tid >> 5;
    const int wm = wid & 3;            // 4 warps along M
    const int wn = wid >> 2;           // 2 warps along N
    const int aw = wm * 32;
    const int bw = wn * 64;

    const int m0 = blockIdx.y * 128;
    const int n0 = blockIdx.x * 128;

    float* bias_s = reinterpret_cast<float*>(smem + BIAS_OFF);
    if (tid < 128) bias_s[tid] = g_bias[n0 + tid];

    auto load_stage = [&](int it, int s) {
        const int kt = it * BK;
        const uint32_t st = sbase + (uint32_t)s * STAGE_BYTES;
#pragma unroll
        for (int i = 0; i < 4; i++) {
            int id = i * NTHREADS + tid;
            int row = id >> 3, c = id & 7;
            uint32_t so = (uint32_t)(row * 128) + (uint32_t)((c ^ (row & 7)) << 4);
            cp_async16(st + OFF_A + so, g_Ah + (size_t)(m0 + row) * K_DIM + kt + c * 8);
        }
#pragma unroll
        for (int i = 0; i < 4; i++) {
            int id = i * NTHREADS + tid;
            int row = id >> 3, c = id & 7;
            uint32_t so = (uint32_t)(row * 128) + (uint32_t)((c ^ (row & 7)) << 4);
            cp_async16(st + OFF_B + so, g_Bh + (size_t)(n0 + row) * K_DIM + kt + c * 8);
        }
        cp_commit();
    };

    float acc[2][8][4];
#pragma unroll
    for (int i = 0; i < 2; i++)
#pragma unroll
        for (int j = 0; j < 8; j++)
#pragma unroll
            for (int q = 0; q < 4; q++) acc[i][j][q] = 0.0f;

    load_stage(0, 0);
    load_stage(1, 1);

    const int aRow = aw + (lane & 15);
    const int aHi = lane >> 4;
    const int bRow = bw + (lane & 7) + ((lane >> 4) << 3);
    const int bHi = (lane >> 3) & 1;

    for (int it = 0; it < NKT; it++) {
        cp_wait<NSTAGES - 2>();        // stage `it` resident
        __syncthreads();               // all warps finished stage it-1

        if (it + NSTAGES - 1 < NKT) load_stage(it + NSTAGES - 1, (it + NSTAGES - 1) % NSTAGES);

        const uint32_t st = sbase + (uint32_t)(it % NSTAGES) * STAGE_BYTES;

#pragma unroll
        for (int ks = 0; ks < BK / 16; ks++) {
            uint32_t aH[2][4], bH[8][2];
#pragma unroll
            for (int mf = 0; mf < 2; mf++) {
                int row = aRow + mf * 16;
                int c = 2 * ks + aHi;
                uint32_t off = row * 128 + ((c ^ (row & 7)) << 4);
                ldsm4(aH[mf][0], aH[mf][1], aH[mf][2], aH[mf][3], st + OFF_A + off);
            }
#pragma unroll
            for (int nf2 = 0; nf2 < 4; nf2++) {
                int row = bRow + nf2 * 16;
                int c = 2 * ks + bHi;
                uint32_t addr = st + OFF_B + row * 128 + ((c ^ (row & 7)) << 4);
                ldsm4(bH[2 * nf2][0], bH[2 * nf2][1], bH[2 * nf2 + 1][0], bH[2 * nf2 + 1][1], addr);
            }
#pragma unroll
            for (int mf = 0; mf < 2; mf++)
#pragma unroll
                for (int nf = 0; nf < 8; nf++)
                    mma16816(acc[mf][nf][0], acc[mf][nf][1], acc[mf][nf][2], acc[mf][nf][3],
                             aH[mf][0], aH[mf][1], aH[mf][2], aH[mf][3], bH[nf][0], bH[nf][1]);
        }
    }
    __syncthreads();

    // ---- fused epilogue: stage acc to smem (bank-swizzled 128-col rows) ----
    float* zs = reinterpret_cast<float*>(smem);      // 128 x 128 fp32 = 64KB
#pragma unroll
    for (int mf = 0; mf < 2; mf++) {
#pragma unroll
        for (int nf = 0; nf < 8; nf++) {
            int r0 = aw + mf * 16 + (lane >> 2);
            int col = bw + nf * 8 + 2 * (lane & 3);
            int c0 = col ^ ((r0 & 7) << 3);
            int c1 = col ^ (((r0 + 8) & 7) << 3);
            *reinterpret_cast<float2*>(&zs[(size_t)r0 * 128 + c0]) =
                make_float2(acc[mf][nf][0], acc[mf][nf][1]);
            *reinterpret_cast<float2*>(&zs[(size_t)(r0 + 8) * 128 + c1]) =
                make_float2(acc[mf][nf][2], acc[mf][nf][3]);
        }
    }
    __syncthreads();

    const int jbase = n0 >> 2;
#pragma unroll 4
    for (int r = 0; r < 16; r++) {
        int idx = r * NTHREADS + tid;
        int ml = idx >> 5;
        int q = idx & 31;
        int cc = (4 * q) ^ ((ml & 7) << 3);
        float4 z4 = *reinterpret_cast<const float4*>(&zs[(size_t)ml * 128 + cc]);
        float zi = z4.x + bias_s[4 * q + 0];
        float zf = z4.y + bias_s[4 * q + 1];
        float zc = z4.z + bias_s[4 * q + 2];
        float zo = z4.w + bias_s[4 * q + 3];
        int m = m0 + ml;
        int j = jbase + q;
        float cp = cprev[(size_t)m * D_H + j];
        float cn = sigm(zf) * cp + sigm(zi) * tanh_fast(zc);
        float hn = sigm(zo) * tanh_fast(cn);
        out[(size_t)m * D_H + j] = hn;
        out[OUT_C_OFF + (size_t)m * D_H + j] = cn;
    }
}

// ---------------- launch ----------------
extern "C" void kernel_launch(void* const* d_in, const int* in_sizes, int n_in,
                              void* d_out, int out_size)
{
    const float* x  = (const float*)d_in[0];
    const float* h  = (const float*)d_in[1];
    const float* c  = (const float*)d_in[2];
    const float* Wi = (const float*)d_in[3];
    const float* bi = (const float*)d_in[4];
    const float* Wf = (const float*)d_in[5];
    const float* bf = (const float*)d_in[6];
    const float* Wc = (const float*)d_in[7];
    const float* bc = (const float*)d_in[8];
    const float* Wo = (const float*)d_in[9];
    const float* bo = (const float*)d_in[10];
    float* out = (float*)d_out;

    static bool attr_set = false;
    if (!attr_set) {
        cudaFuncSetAttribute(lstm_fused, cudaFuncAttributeMaxDynamicSharedMemorySize, SMEM_TOTAL);
        attr_set = true;
    }

    conv_all<<<8208, 256>>>(x, h, Wi, Wf, Wc, Wo, bi, bf, bc, bo);

    dim3 grid(N_DIM / 128, B_ROWS / 128);   // 32 x 32 = 1024 CTAs
    lstm_fused<<<grid, NTHREADS, SMEM_TOTAL>>>(c, out);
}

// round 16
// speedup vs baseline: 1.0601x; 1.0154x over previous
#include <cuda_runtime.h>
#include <cuda_fp16.h>
#include <math.h>
#include <stdint.h>

#define B_ROWS 4096
#define D_H    1024
#define K_DIM  2048
#define N_DIM  4096

// ---------------- static device scratch ----------------
__device__ __align__(128) __half g_Ah[(size_t)B_ROWS * K_DIM];
__device__ __align__(128) __half g_Bh[(size_t)N_DIM * K_DIM];   // interleaved rows n' = 4j+g
__device__ __align__(128) float  g_bias[N_DIM];                 // interleaved

// ---------------- helpers ----------------
__device__ __forceinline__ uint32_t smem_u32(const void* p) {
    uint32_t a;
    asm("{ .reg .u64 t; cvta.to.shared.u64 t, %1; cvt.u32.u64 %0, t; }" : "=r"(a) : "l"(p));
    return a;
}
__device__ __forceinline__ void cp_async16(uint32_t dst, const void* src) {
    asm volatile("cp.async.cg.shared.global [%0], [%1], 16;" :: "r"(dst), "l"(src) : "memory");
}
__device__ __forceinline__ void cp_commit() {
    asm volatile("cp.async.commit_group;" ::: "memory");
}
template <int N>
__device__ __forceinline__ void cp_wait() {
    asm volatile("cp.async.wait_group %0;" :: "n"(N) : "memory");
}
__device__ __forceinline__ void ldsm4(uint32_t& r0, uint32_t& r1, uint32_t& r2, uint32_t& r3,
                                      uint32_t addr) {
    asm volatile("ldmatrix.sync.aligned.m8n8.x4.shared.b16 {%0,%1,%2,%3}, [%4];"
                 : "=r"(r0), "=r"(r1), "=r"(r2), "=r"(r3) : "r"(addr));
}
__device__ __forceinline__ void mma16816(float& d0, float& d1, float& d2, float& d3,
                                         uint32_t a0, uint32_t a1, uint32_t a2, uint32_t a3,
                                         uint32_t b0, uint32_t b1) {
    asm volatile(
        "mma.sync.aligned.m16n8k16.row.col.f32.f16.f16.f32 "
        "{%0,%1,%2,%3}, {%4,%5,%6,%7}, {%8,%9}, {%0,%1,%2,%3};"
        : "+f"(d0), "+f"(d1), "+f"(d2), "+f"(d3)
        : "r"(a0), "r"(a1), "r"(a2), "r"(a3), "r"(b0), "r"(b1));
}

__device__ __forceinline__ float sigm(float z) { return 1.0f / (1.0f + __expf(-z)); }
__device__ __forceinline__ float tanh_fast(float z) {
    return 2.0f / (1.0f + __expf(-2.0f * z)) - 1.0f;
}

// ---------------- merged conversion kernel (one launch, 8 floats/thread) ----
__global__ __launch_bounds__(256) void conv_all(
    const float* __restrict__ x, const float* __restrict__ h,
    const float* __restrict__ Wi, const float* __restrict__ Wf,
    const float* __restrict__ Wc, const float* __restrict__ Wo,
    const float* __restrict__ bi, const float* __restrict__ bf_,
    const float* __restrict__ bc, const float* __restrict__ bo)
{
    const int b = blockIdx.x;
    if (b < 8192) {
        const bool isA = (b < 4096);
        size_t e = ((size_t)(isA ? b : b - 4096) * 256 + threadIdx.x) * 8;
        int r = (int)(e >> 11);          // row (m for A, n' for B)
        int k = (int)(e & 2047);         // 8-aligned; never straddles 1024
        const float* src;
        if (isA) {
            src = (k < 1024) ? &x[(size_t)r * 1024 + k]
                             : &h[(size_t)r * 1024 + (k - 1024)];
        } else {
            int j = r >> 2;
            int g = r & 3;
            const float* W = (g == 0) ? Wi : (g == 1) ? Wf : (g == 2) ? Wc : Wo;
            src = &W[(size_t)j * K_DIM + k];
        }
        float4 v0 = *reinterpret_cast<const float4*>(src);
        float4 v1 = *reinterpret_cast<const float4*>(src + 4);
        __half2 o[4];
        o[0] = __halves2half2(__float2half_rn(v0.x), __float2half_rn(v0.y));
        o[1] = __halves2half2(__float2half_rn(v0.z), __float2half_rn(v0.w));
        o[2] = __halves2half2(__float2half_rn(v1.x), __float2half_rn(v1.y));
        o[3] = __halves2half2(__float2half_rn(v1.z), __float2half_rn(v1.w));
        __half* dst = isA ? g_Ah : g_Bh;
        *reinterpret_cast<uint4*>(&dst[e]) = *reinterpret_cast<const uint4*>(o);
    } else {
        int idx = (b - 8192) * 256 + threadIdx.x;
        int j = idx >> 2;
        int g = idx & 3;
        g_bias[idx] = (g == 0) ? bi[j] : (g == 1) ? bf_[j] : (g == 2) ? bc[j] : bo[j];
    }
}

// ---------------- fused GEMM + LSTM (R8 core, barrier moved to ks3) --------
// CTA 128x128, 8 warps (4M x 2N, warp tile 32x64), BK=64, 3-slot ring, 2 CTAs/SM.
// Invariant preserved: every cross-stage smem read happens after cp_wait + BARRIER.
// The barrier sits at ks==3 where the pending MMA operands are already in regs,
// so post-barrier tensor issue resumes immediately.
#define BK 64
#define OFF_A 0
#define OFF_B 16384
#define STAGE_BYTES 32768
#define NSTAGES 3
#define BIAS_OFF    (NSTAGES * STAGE_BYTES)     // 98304
#define SMEM_TOTAL  (BIAS_OFF + 512)            // 98816
#define NKT (K_DIM / BK)           // 32
#define NTHREADS 256
#define OUT_C_OFF ((size_t)B_ROWS * D_H)

__global__ __launch_bounds__(NTHREADS, 2) void lstm_fused(const float* __restrict__ cprev,
                                                          float* __restrict__ out) {
    extern __shared__ char smem[];
    const uint32_t sbase = smem_u32(smem);
    const int tid = threadIdx.x;
    const int lane = tid & 31;
    const int wid = tid >> 5;
    const int wm = wid & 3;            // 4 warps along M
    const int wn = wid >> 2;           // 2 warps along N
    const int aw = wm * 32;
    const int bw = wn * 64;

    const int m0 = blockIdx.y * 128;
    const int n0 = blockIdx.x * 128;

    float* bias_s = reinterpret_cast<float*>(smem + BIAS_OFF);
    if (tid < 128) bias_s[tid] = g_bias[n0 + tid];

    auto load_stage = [&](int it, int s) {
        const int kt = it * BK;
        const uint32_t st = sbase + (uint32_t)s * STAGE_BYTES;
#pragma unroll
        for (int i = 0; i < 4; i++) {
            int id = i * NTHREADS + tid;
            int row = id >> 3, c = id & 7;
            uint32_t so = (uint32_t)(row * 128) + (uint32_t)((c ^ (row & 7)) << 4);
            cp_async16(st + OFF_A + so, g_Ah + (size_t)(m0 + row) * K_DIM + kt + c * 8);
        }
#pragma unroll
        for (int i = 0; i < 4; i++) {
            int id = i * NTHREADS + tid;
            int row = id >> 3, c = id & 7;
            uint32_t so = (uint32_t)(row * 128) + (uint32_t)((c ^ (row & 7)) << 4);
            cp_async16(st + OFF_B + so, g_Bh + (size_t)(n0 + row) * K_DIM + kt + c * 8);
        }
        cp_commit();
    };

    float acc[2][8][4];
#pragma unroll
    for (int i = 0; i < 2; i++)
#pragma unroll
        for (int j = 0; j < 8; j++)
#pragma unroll
            for (int q = 0; q < 4; q++) acc[i][j][q] = 0.0f;

    load_stage(0, 0);
    load_stage(1, 1);

    const int aRow = aw + (lane & 15);
    const int aHi = lane >> 4;
    const int bRow = bw + (lane & 7) + ((lane >> 4) << 3);
    const int bHi = (lane >> 3) & 1;

    // fragment double buffers (bridge the barrier)
    uint32_t fa[2][2][4];
    uint32_t fb[2][8][2];

    auto load_frags = [&](uint32_t st, int ks, int bsel) {
#pragma unroll
        for (int mf = 0; mf < 2; mf++) {
            int row = aRow + mf * 16;
            int c = 2 * ks + aHi;
            uint32_t off = row * 128 + ((c ^ (row & 7)) << 4);
            ldsm4(fa[bsel][mf][0], fa[bsel][mf][1], fa[bsel][mf][2], fa[bsel][mf][3],
                  st + OFF_A + off);
        }
#pragma unroll
        for (int nf2 = 0; nf2 < 4; nf2++) {
            int row = bRow + nf2 * 16;
            int c = 2 * ks + bHi;
            uint32_t addr = st + OFF_B + row * 128 + ((c ^ (row & 7)) << 4);
            ldsm4(fb[bsel][2 * nf2][0], fb[bsel][2 * nf2][1],
                  fb[bsel][2 * nf2 + 1][0], fb[bsel][2 * nf2 + 1][1], addr);
        }
    };

    // prime: wait for group 0 (this thread), BARRIER (publishes all threads'
    // group-0 copies), then load stage-0 ks0 frags.
    cp_wait<1>();
    __syncthreads();
    load_frags(sbase, 0, 0);

    for (int it = 0; it < NKT; it++) {
        // slot (it+2)%3 == slot (it-1)%3: its last readers (frag loads of stage
        // it-1) all finished before the previous tail barrier.
        if (it + 2 < NKT) load_stage(it + 2, (it + 2) % NSTAGES);
        else cp_commit();              // empty group keeps wait<1> accounting exact

        const uint32_t st = sbase + (uint32_t)(it % NSTAGES) * STAGE_BYTES;
        const uint32_t stn = sbase + (uint32_t)((it + 1) % NSTAGES) * STAGE_BYTES;

#pragma unroll
        for (int ks = 0; ks < BK / 16; ks++) {
            const int cur = ks & 1;
            if (ks < 3) {
                load_frags(st, ks + 1, cur ^ 1);       // same-stage: already published
            } else if (it + 1 < NKT) {
                cp_wait<1>();          // this thread's group it+1 complete
                __syncthreads();       // ALL threads' group it+1 complete -> published
                load_frags(stn, 0, cur ^ 1);           // safe cross-stage read
            }
            // ks3 MMAs issue right after the barrier from registers (cur buffer)
#pragma unroll
            for (int mf = 0; mf < 2; mf++)
#pragma unroll
                for (int nf = 0; nf < 8; nf++)
                    mma16816(acc[mf][nf][0], acc[mf][nf][1], acc[mf][nf][2], acc[mf][nf][3],
                             fa[cur][mf][0], fa[cur][mf][1], fa[cur][mf][2], fa[cur][mf][3],
                             fb[cur][nf][0], fb[cur][nf][1]);
        }
    }
    __syncthreads();

    // ---- fused epilogue: stage acc to smem (bank-swizzled 128-col rows) ----
    float* zs = reinterpret_cast<float*>(smem);      // 128 x 128 fp32 = 64KB
#pragma unroll
    for (int mf = 0; mf < 2; mf++) {
#pragma unroll
        for (int nf = 0; nf < 8; nf++) {
            int r0 = aw + mf * 16 + (lane >> 2);
            int col = bw + nf * 8 + 2 * (lane & 3);
            int c0 = col ^ ((r0 & 7) << 3);
            int c1 = col ^ (((r0 + 8) & 7) << 3);
            *reinterpret_cast<float2*>(&zs[(size_t)r0 * 128 + c0]) =
                make_float2(acc[mf][nf][0], acc[mf][nf][1]);
            *reinterpret_cast<float2*>(&zs[(size_t)(r0 + 8) * 128 + c1]) =
                make_float2(acc[mf][nf][2], acc[mf][nf][3]);
        }
    }
    __syncthreads();

    const int jbase = n0 >> 2;
#pragma unroll 4
    for (int r = 0; r < 16; r++) {
        int idx = r * NTHREADS + tid;
        int ml = idx >> 5;
        int q = idx & 31;
        int cc = (4 * q) ^ ((ml & 7) << 3);
        float4 z4 = *reinterpret_cast<const float4*>(&zs[(size_t)ml * 128 + cc]);
        float zi = z4.x + bias_s[4 * q + 0];
        float zf = z4.y + bias_s[4 * q + 1];
        float zc = z4.z + bias_s[4 * q + 2];
        float zo = z4.w + bias_s[4 * q + 3];
        int m = m0 + ml;
        int j = jbase + q;
        float cp = cprev[(size_t)m * D_H + j];
        float cn = sigm(zf) * cp + sigm(zi) * tanh_fast(zc);
        float hn = sigm(zo) * tanh_fast(cn);
        out[(size_t)m * D_H + j] = hn;
        out[OUT_C_OFF + (size_t)m * D_H + j] = cn;
    }
}

// ---------------- launch ----------------
extern "C" void kernel_launch(void* const* d_in, const int* in_sizes, int n_in,
                              void* d_out, int out_size)
{
    const float* x  = (const float*)d_in[0];
    const float* h  = (const float*)d_in[1];
    const float* c  = (const float*)d_in[2];
    const float* Wi = (const float*)d_in[3];
    const float* bi = (const float*)d_in[4];
    const float* Wf = (const float*)d_in[5];
    const float* bf = (const float*)d_in[6];
    const float* Wc = (const float*)d_in[7];
    const float* bc = (const float*)d_in[8];
    const float* Wo = (const float*)d_in[9];
    const float* bo = (const float*)d_in[10];
    float* out = (float*)d_out;

    static bool attr_set = false;
    if (!attr_set) {
        cudaFuncSetAttribute(lstm_fused, cudaFuncAttributeMaxDynamicSharedMemorySize, SMEM_TOTAL);
        attr_set = true;
    }

    conv_all<<<8208, 256>>>(x, h, Wi, Wf, Wc, Wo, bi, bf, bc, bo);

    dim3 grid(N_DIM / 128, B_ROWS / 128);   // 32 x 32 = 1024 CTAs
    lstm_fused<<<grid, NTHREADS, SMEM_TOTAL>>>(c, out);
}